// round 16
// baseline (speedup 1.0000x reference)
#include <cuda_runtime.h>
#include <math.h>
#include <stdint.h>

#define NB 8
#define NT 2048
#define NC 2048
#define NHS 128
#define NM (NB*NT)

// scratch
__device__ uint32_t g_qh[(size_t)NM*64];              // q bf16-hi, pair-permuted, pre-scaled
__device__ uint32_t g_ql[(size_t)NM*64];              // q bf16-lo
__device__ uint32_t g_kh[(size_t)NM*64];              // k bf16-hi
__device__ uint32_t g_kl[(size_t)NM*64];              // k bf16-lo
__device__ float g_vT[(size_t)NB*NHS*NT];             // v^T, tf32-rounded, vmap key order
__device__ float g_cos[NT*64];
__device__ float g_sin[NT*64];
__device__ float g_wp[(size_t)3*NC*NHS];              // W, fragment-permuted + tf32-rounded
__device__ float g_pO[(size_t)2*NM*NHS];              // split-KV partial O
__device__ float g_pm[2*NM];                          // partial row max
__device__ float g_pl[2*NM];                          // partial row sum

__device__ __forceinline__ uint32_t f2tf(float f) {
    uint32_t r;
    asm("cvt.rna.tf32.f32 %0, %1;" : "=r"(r) : "f"(f));
    return r;
}
__device__ __forceinline__ float tf32r(float f) {
    return __uint_as_float(f2tf(f));
}
__device__ __forceinline__ uint32_t bfpack(float lo, float hi) {
    uint32_t r;   // lo -> bits 0-15, hi -> bits 16-31
    asm("cvt.rn.bf16x2.f32 %0, %1, %2;" : "=r"(r) : "f"(hi), "f"(lo));
    return r;
}

__device__ __forceinline__ void mma_tf32(float c[4], const uint32_t a[4],
                                         const uint32_t b[2]) {
    asm volatile(
        "mma.sync.aligned.m16n8k8.row.col.f32.tf32.tf32.f32 "
        "{%0,%1,%2,%3}, {%4,%5,%6,%7}, {%8,%9}, {%0,%1,%2,%3};"
        : "+f"(c[0]), "+f"(c[1]), "+f"(c[2]), "+f"(c[3])
        : "r"(a[0]), "r"(a[1]), "r"(a[2]), "r"(a[3]),
          "r"(b[0]), "r"(b[1]));
}
__device__ __forceinline__ void mma_bf16(float c[4], const uint32_t a[4],
                                         const uint32_t b[2]) {
    asm volatile(
        "mma.sync.aligned.m16n8k16.row.col.f32.bf16.bf16.f32 "
        "{%0,%1,%2,%3}, {%4,%5,%6,%7}, {%8,%9}, {%0,%1,%2,%3};"
        : "+f"(c[0]), "+f"(c[1]), "+f"(c[2]), "+f"(c[3])
        : "r"(a[0]), "r"(a[1]), "r"(a[2]), "r"(a[3]),
          "r"(b[0]), "r"(b[1]));
}

__device__ __forceinline__ uint32_t smem_u32(const void* p) {
    uint32_t a;
    asm("{ .reg .u64 t; cvta.to.shared.u64 t, %1; cvt.u32.u64 %0, t; }"
        : "=r"(a) : "l"(p));
    return a;
}

__device__ __forceinline__ void cp16(uint32_t dst, const void* src) {
    asm volatile("cp.async.cg.shared.global [%0], [%1], 16;"
                 :: "r"(dst), "l"(src) : "memory");
}
#define CP_COMMIT() asm volatile("cp.async.commit_group;" ::: "memory")
#define CP_WAIT(n)  asm volatile("cp.async.wait_group %0;" :: "n"(n) : "memory")

// pair layout: word(row, fp) holds bf16x2 of features {2fp, 2fp+1};
// q = 8*(fp>>3) + 2*(fp&3) + ((fp>>2)&1)  (bijective onto [0,64)).
__device__ __forceinline__ int qmap(int fp) {
    return 8 * (fp >> 3) + 2 * (fp & 3) + ((fp >> 2) & 1);
}
__device__ __forceinline__ int swz(int q, int row) {
    return q ^ ((q >> 2) & 0x18) ^ ((row & 3) << 3);
}
// V key permute within 64-chunk: keys (8k+t, 8k+t+4) become adjacent words.
__device__ __forceinline__ int vmap(int kl) {
    return (kl & ~7) + ((kl & 3) << 1) + ((kl >> 2) & 1);
}

// ---------------------------------------------------------------------------
// RoPE tables                                                   (launch #1)
// ---------------------------------------------------------------------------
__global__ void rope_table_kernel()
{
    int idx = blockIdx.x * 256 + threadIdx.x;
    if (idx >= NT * 64) return;
    int tt = idx >> 6, p = idx & 63;
    const float L2T = 13.287712379549449f / 64.f;   // log2(10000)/64
    float freq = exp2f(-(float)p * L2T);
    float sn, cs;
    sincosf((float)tt * freq, &sn, &cs);
    g_cos[idx] = cs;
    g_sin[idx] = sn;
}

// ---------------------------------------------------------------------------
// prep_w                                                        (launch #2)
// ---------------------------------------------------------------------------
#define PWSTR 136
__global__ __launch_bounds__(256) void prep_w(
    const float* __restrict__ Wk, const float* __restrict__ Wq,
    const float* __restrict__ Wv)
{
    __shared__ float s[32 * PWSTR];
    const int tid = threadIdx.x;
    const int kit = blockIdx.x, which = blockIdx.y;
    const float* W = (which == 0) ? Wk : (which == 1) ? Wq : Wv;

    #pragma unroll
    for (int u = 0; u < 4; u++) {
        int flat = u * 256 + tid;
        int row = flat >> 5, cf = flat & 31;
        float4 v = *reinterpret_cast<const float4*>(
            &W[(size_t)(kit * 32 + row) * NHS + cf * 4]);
        *reinterpret_cast<float4*>(&s[row * PWSTR + cf * 4]) = v;
    }
    __syncthreads();

    const size_t base = ((size_t)(which * 64 + kit)) * 4096;
    #pragma unroll
    for (int u = 0; u < 8; u++) {
        int pid = u * 256 + tid;
        int lane = pid & 31, ks = (pid >> 5) & 3, in = (pid >> 7) & 3, wn = pid >> 9;
        int g = lane >> 2, t = lane & 3;
        int n0 = wn * 32 + in * 8 + g, c = ks * 8 + t;
        float2 o;
        o.x = tf32r(s[(c    ) * PWSTR + n0]);
        o.y = tf32r(s[(c + 4) * PWSTR + n0]);
        *reinterpret_cast<float2*>(&g_wp[base + (size_t)pid * 2]) = o;
    }
}

// ---------------------------------------------------------------------------
// Kernel A: fused projection + RoPE; epilogue emits attn-ready  (launch #3)
// formats: q/k as bf16 hi/lo pair-permuted, v^T tf32 + vmap.
// ---------------------------------------------------------------------------
#define AQW 4096
#define BQW 4096
#define PROJ_SMEM ((2*AQW + 3*BQW)*4)
#define NITER (NC/32)

__global__ __launch_bounds__(256, 2) void proj_cp(const float* __restrict__ x)
{
    extern __shared__ float sm[];
    const uint32_t sbase = smem_u32(sm);
    const uint32_t sA0 = sbase;
    const uint32_t sB0 = sbase + 2 * AQW * 4;

    const int tid  = threadIdx.x;
    const int warp = tid >> 5, lane = tid & 31;
    const int wm = warp >> 2, wn = warp & 3;
    const int g = lane >> 2, t = lane & 3;
    const int mtile = blockIdx.x, which = blockIdx.y;
    const int mbase = mtile * 128;

    const int im_s = warp & 3;
    const size_t arow0 = (size_t)(mbase + wm * 64 + im_s * 16 + g) * NC;
    const size_t arow8 = arow0 + (size_t)8 * NC;
    const int akc = t * 8;
    uint32_t asts[4];
    #pragma unroll
    for (int tt = 0; tt < 4; tt++)
        asts[tt] = (uint32_t)((((wm * 4 + im_s) * 4 + t) * 32 +
                               ((g * 4 + tt) ^ t)) * 16);

    const float* wp = &g_wp[((size_t)which * 64) * 4096];

    float c[4][4][4];
    #pragma unroll
    for (int im = 0; im < 4; im++)
        #pragma unroll
        for (int in = 0; in < 4; in++)
            #pragma unroll
            for (int f = 0; f < 4; f++) c[im][in][f] = 0.f;

    float4 f0, f1, f2, f3;
    auto ldgA = [&](int it) {
        const int kc = it * 32 + akc;
        f0 = *reinterpret_cast<const float4*>(&x[arow0 + kc]);
        f1 = *reinterpret_cast<const float4*>(&x[arow0 + kc + 4]);
        f2 = *reinterpret_cast<const float4*>(&x[arow8 + kc]);
        f3 = *reinterpret_cast<const float4*>(&x[arow8 + kc + 4]);
    };
    auto stsA = [&](int buf) {
        const uint32_t base = sA0 + (uint32_t)buf * (AQW * 4);
        const float a0[4] = {f0.x, f0.y, f0.z, f0.w};
        const float a1[4] = {f1.x, f1.y, f1.z, f1.w};
        const float a2[4] = {f2.x, f2.y, f2.z, f2.w};
        const float a3[4] = {f3.x, f3.y, f3.z, f3.w};
        #pragma unroll
        for (int tt = 0; tt < 4; tt++) {
            uint32_t qx = f2tf(a0[tt]), qy = f2tf(a2[tt]);
            uint32_t qz = f2tf(a1[tt]), qw = f2tf(a3[tt]);
            asm volatile("st.shared.v4.b32 [%0], {%1,%2,%3,%4};"
                         :: "r"(base + asts[tt]),
                            "r"(qx), "r"(qy), "r"(qz), "r"(qw) : "memory");
        }
    };
    auto stageB = [&](int it, int s) {
        const uint32_t bb = sB0 + (uint32_t)s * (BQW * 4);
        const float* wt = wp + (size_t)it * 4096;
        #pragma unroll
        for (int u = 0; u < 4; u++) {
            int idx = u * 256 + tid;
            cp16(bb + (uint32_t)idx * 16, wt + idx * 4);
        }
        CP_COMMIT();
    };

    stageB(0, 0);
    stageB(1, 1);
    ldgA(0);

    for (int it = 0; it < NITER; it++) {
        stsA(it & 1);
        if (it == NITER - 1) { CP_WAIT(0); } else { CP_WAIT(1); }
        __syncthreads();
        if (it + 1 < NITER) ldgA(it + 1);
        if (it + 2 < NITER) stageB(it + 2, (it + 2) % 3);

        const uint32_t aB = sA0 + (uint32_t)(it & 1) * (AQW * 4);
        const uint32_t bB = sB0 + (uint32_t)(it % 3) * (BQW * 4);

        #pragma unroll
        for (int ks = 0; ks < 4; ks++) {
            uint32_t afr[4][4];
            #pragma unroll
            for (int im = 0; im < 4; im++) {
                uint32_t ad = aB + (uint32_t)((((wm * 4 + im) * 4 + ks) * 32 +
                                               (lane ^ ks)) * 16);
                asm volatile("ld.shared.v4.b32 {%0,%1,%2,%3}, [%4];"
                             : "=r"(afr[im][0]), "=r"(afr[im][1]),
                               "=r"(afr[im][2]), "=r"(afr[im][3])
                             : "r"(ad));
            }
            uint32_t bfr[4][2];
            #pragma unroll
            for (int in = 0; in < 4; in++) {
                uint32_t bd = bB + (uint32_t)((((wn * 4 + in) * 4 + ks) * 32 +
                                               lane) * 8);
                asm volatile("ld.shared.v2.b32 {%0,%1}, [%2];"
                             : "=r"(bfr[in][0]), "=r"(bfr[in][1])
                             : "r"(bd));
            }
            #pragma unroll
            for (int im = 0; im < 4; im++)
                #pragma unroll
                for (int in = 0; in < 4; in++)
                    mma_tf32(c[im][in], afr[im], bfr[in]);
        }
    }

    // epilogue -> attn-ready formats
    const float qs = 0.08838834764831845f * 1.4426950408889634f;
    #pragma unroll
    for (int im = 0; im < 4; im++) {
        int r1 = mbase + wm * 64 + im * 16 + g;
        int r2 = r1 + 8;
        int bb = r1 >> 11;
        int t1 = r1 & (NT - 1), t2 = r2 & (NT - 1);
        if (which == 2) {
            int p1 = (t1 & ~63) + vmap(t1 & 63);
            int p2 = (t2 & ~63) + vmap(t2 & 63);
            #pragma unroll
            for (int in = 0; in < 4; in++) {
                int n = wn * 32 + in * 8 + 2 * t;
                size_t b0 = ((size_t)bb * NHS + n) * NT;
                size_t b1 = ((size_t)bb * NHS + n + 1) * NT;
                g_vT[b0 + p1] = tf32r(c[im][in][0]);
                g_vT[b1 + p1] = tf32r(c[im][in][1]);
                g_vT[b0 + p2] = tf32r(c[im][in][2]);
                g_vT[b1 + p2] = tf32r(c[im][in][3]);
            }
        } else {
            uint32_t* oh = (which == 1) ? g_qh : g_kh;
            uint32_t* ol = (which == 1) ? g_ql : g_kl;
            #pragma unroll
            for (int in2 = 0; in2 < 4; in2 += 2) {
                uint32_t h1[2], l1[2], h2[2], l2[2];
                #pragma unroll
                for (int j = 0; j < 2; j++) {
                    int in = in2 + j;
                    int n = wn * 32 + in * 8 + 2 * t;
                    int p = n >> 1;
                    float cs1 = g_cos[t1 * 64 + p], sn1 = g_sin[t1 * 64 + p];
                    float cs2 = g_cos[t2 * 64 + p], sn2 = g_sin[t2 * 64 + p];
                    float e0 = c[im][in][0] * cs1 - c[im][in][1] * sn1;
                    float e1 = c[im][in][0] * sn1 + c[im][in][1] * cs1;
                    float d0 = c[im][in][2] * cs2 - c[im][in][3] * sn2;
                    float d1 = c[im][in][2] * sn2 + c[im][in][3] * cs2;
                    if (which == 1) { e0 *= qs; e1 *= qs; d0 *= qs; d1 *= qs; }
                    uint32_t hh = bfpack(e0, e1);
                    h1[j] = hh;
                    l1[j] = bfpack(e0 - __uint_as_float(hh << 16),
                                   e1 - __uint_as_float(hh & 0xffff0000u));
                    hh = bfpack(d0, d1);
                    h2[j] = hh;
                    l2[j] = bfpack(d0 - __uint_as_float(hh << 16),
                                   d1 - __uint_as_float(hh & 0xffff0000u));
                }
                int w = qmap((wn * 32 + in2 * 8 + 2 * t) >> 1);
                *reinterpret_cast<uint2*>(&oh[(size_t)r1 * 64 + w]) = make_uint2(h1[0], h1[1]);
                *reinterpret_cast<uint2*>(&ol[(size_t)r1 * 64 + w]) = make_uint2(l1[0], l1[1]);
                *reinterpret_cast<uint2*>(&oh[(size_t)r2 * 64 + w]) = make_uint2(h2[0], h2[1]);
                *reinterpret_cast<uint2*>(&ol[(size_t)r2 * 64 + w]) = make_uint2(l2[0], l2[1]);
            }
        }
    }
}

// ---------------------------------------------------------------------------
// Kernel B: causal flash attention, split-KV 2-way.             (launch #4)
// All operands pre-formatted by proj -> staging is pure cp.async.
// ---------------------------------------------------------------------------
#define QH0 0
#define QL0 8192
#define KH0 16384
#define KL0 20480
#define VT0 24576
#define P0  33280
#define ATTN_SMEM_BYTES ((P0 + 8704) * 4)

__global__ __launch_bounds__(256) void attn_mma()
{
    extern __shared__ char smem_raw[];
    const uint32_t sb = smem_u32(smem_raw);
    uint32_t* sQh = (uint32_t*)smem_raw;
    uint32_t* sQl = sQh + QL0;
    uint32_t* sKh = sQh + KH0;
    uint32_t* sKl = sQh + KL0;
    uint32_t* sVT = sQh + VT0;
    uint32_t* sP  = sQh + P0;

    const int tid  = threadIdx.x;
    const int warp = tid >> 5, lane = tid & 31;
    const int g = lane >> 2, t = lane & 3;
    const int r0 = warp * 16;

    const int bx = blockIdx.x;
    const int qi   = 15 - (bx >> 4);          // largest tiles first (LPT)
    const int yb   = (bx >> 1) & 7;
    const int half = bx & 1;
    const int q0 = qi * 128;
    const int c0 = half * (qi + 1);
    const size_t rowbase = (size_t)yb * NT;

    // ---- stage Q once (pure cp.async) ----
    const size_t qsrc = (size_t)(rowbase + q0) * 64;
    #pragma unroll
    for (int u = 0; u < 8; u++) {
        int id = u * 256 + tid;
        int row = id >> 4, grp = (id & 15) * 4;
        uint32_t woff = (uint32_t)(row * 64 + swz(grp, row));
        cp16(sb + (QH0 + woff) * 4, &g_qh[qsrc + (size_t)row * 64 + grp]);
        cp16(sb + (QL0 + woff) * 4, &g_ql[qsrc + (size_t)row * 64 + grp]);
    }
    CP_COMMIT();

    float m_lo = -1e30f, m_hi = -1e30f, l_lo = 0.f, l_hi = 0.f;
    float o[16][4];
    #pragma unroll
    for (int nt = 0; nt < 16; nt++)
        #pragma unroll
        for (int f = 0; f < 4; f++) o[nt][f] = 0.f;

    for (int ci = 0; ci <= qi; ci++) {
        const int c = c0 + ci;
        __syncthreads();
        // ---- stage K + V chunk (pure cp.async) ----
        const size_t ksrc = (size_t)(rowbase + c * 64) * 64;
        #pragma unroll
        for (int u = 0; u < 4; u++) {
            int id = u * 256 + tid;
            int row = id >> 4, grp = (id & 15) * 4;
            uint32_t woff = (uint32_t)(row * 64 + swz(grp, row));
            cp16(sb + (KH0 + woff) * 4, &g_kh[ksrc + (size_t)row * 64 + grp]);
            cp16(sb + (KL0 + woff) * 4, &g_kl[ksrc + (size_t)row * 64 + grp]);
        }
        const float* vsrc = &g_vT[(size_t)yb * NHS * NT + (size_t)c * 64];
        #pragma unroll
        for (int u = 0; u < 8; u++) {
            int id = u * 256 + tid;
            int hr = id >> 4, kf = (id & 15) * 4;
            cp16(sb + (uint32_t)(VT0 + hr * 68 + kf) * 4, vsrc + (size_t)hr * NT + kf);
        }
        CP_COMMIT();
        CP_WAIT(0);
        __syncthreads();

        // ---- S = QK^T (bf16 split, m16n8k16) ----
        float s[8][4];
        #pragma unroll
        for (int in = 0; in < 8; in++)
            #pragma unroll
            for (int f = 0; f < 4; f++) s[in][f] = 0.f;

        #pragma unroll
        for (int kst = 0; kst < 8; kst++) {
            const int qa = 8 * kst + 2 * t;
            uint32_t ah[4], al[4];
            {
                int r1 = r0 + g;
                int w = r1 * 64 + swz(qa, r1);
                uint2 vh = *reinterpret_cast<uint2*>(sQh + w);
                uint2 vl = *reinterpret_cast<uint2*>(sQl + w);
                ah[0] = vh.x; ah[2] = vh.y; al[0] = vl.x; al[2] = vl.y;
                int r2 = r1 + 8;
                int w2 = r2 * 64 + swz(qa, r2);
                vh = *reinterpret_cast<uint2*>(sQh + w2);
                vl = *reinterpret_cast<uint2*>(sQl + w2);
                ah[1] = vh.x; ah[3] = vh.y; al[1] = vl.x; al[3] = vl.y;
            }
            #pragma unroll
            for (int in = 0; in < 8; in++) {
                int key = in * 8 + g;
                int w = key * 64 + swz(qa, key);
                uint2 bh = *reinterpret_cast<uint2*>(sKh + w);
                uint2 bl = *reinterpret_cast<uint2*>(sKl + w);
                mma_bf16(s[in], ah, reinterpret_cast<uint32_t*>(&bh));
                mma_bf16(s[in], ah, reinterpret_cast<uint32_t*>(&bl));
                mma_bf16(s[in], al, reinterpret_cast<uint32_t*>(&bh));
            }
        }

        // causal mask
        if (c >= 2 * qi) {
            int qlo = q0 + r0 + g, qhi = qlo + 8;
            int k0c = c * 64;
            #pragma unroll
            for (int in = 0; in < 8; in++) {
                int key0 = k0c + in * 8 + 2 * t;
                if (key0     > qlo) s[in][0] = -1e30f;
                if (key0 + 1 > qlo) s[in][1] = -1e30f;
                if (key0     > qhi) s[in][2] = -1e30f;
                if (key0 + 1 > qhi) s[in][3] = -1e30f;
            }
        }

        // ---- online softmax ----
        float mxl = -1e30f, mxh = -1e30f;
        #pragma unroll
        for (int in = 0; in < 8; in++) {
            mxl = fmaxf(mxl, fmaxf(s[in][0], s[in][1]));
            mxh = fmaxf(mxh, fmaxf(s[in][2], s[in][3]));
        }
        mxl = fmaxf(mxl, __shfl_xor_sync(0xffffffffu, mxl, 1));
        mxl = fmaxf(mxl, __shfl_xor_sync(0xffffffffu, mxl, 2));
        mxh = fmaxf(mxh, __shfl_xor_sync(0xffffffffu, mxh, 1));
        mxh = fmaxf(mxh, __shfl_xor_sync(0xffffffffu, mxh, 2));

        float mnl = fmaxf(fmaxf(m_lo, mxl), -1e20f);
        float mnh = fmaxf(fmaxf(m_hi, mxh), -1e20f);
        float facl = exp2f(m_lo - mnl), fach = exp2f(m_hi - mnh);
        m_lo = mnl; m_hi = mnh;

        float suml = 0.f, sumh = 0.f;
        #pragma unroll
        for (int in = 0; in < 8; in++) {
            float p0 = exp2f(s[in][0] - mnl);
            float p1 = exp2f(s[in][1] - mnl);
            float p2 = exp2f(s[in][2] - mnh);
            float p3 = exp2f(s[in][3] - mnh);
            suml += p0 + p1; sumh += p2 + p3;
            uint2 w0; w0.x = f2tf(p0); w0.y = f2tf(p1);
            uint2 w1; w1.x = f2tf(p2); w1.y = f2tf(p3);
            *reinterpret_cast<uint2*>(&sP[(r0 + g    ) * 68 + in * 8 + 2 * t]) = w0;
            *reinterpret_cast<uint2*>(&sP[(r0 + g + 8) * 68 + in * 8 + 2 * t]) = w1;
        }
        suml += __shfl_xor_sync(0xffffffffu, suml, 1);
        suml += __shfl_xor_sync(0xffffffffu, suml, 2);
        sumh += __shfl_xor_sync(0xffffffffu, sumh, 1);
        sumh += __shfl_xor_sync(0xffffffffu, sumh, 2);
        l_lo = l_lo * facl + suml;
        l_hi = l_hi * fach + sumh;

        // rescale O only if some row max moved (exp2f(0)==1 exact)
        bool nochg = (facl == 1.f) && (fach == 1.f);
        if (__ballot_sync(0xffffffffu, nochg) != 0xffffffffu) {
            #pragma unroll
            for (int nt = 0; nt < 16; nt++) {
                o[nt][0] *= facl; o[nt][1] *= facl;
                o[nt][2] *= fach; o[nt][3] *= fach;
            }
        }
        __syncwarp();

        // ---- O += P V (tf32 k8, vmap-paired b loads) ----
        #pragma unroll
        for (int kk = 0; kk < 8; kk++) {
            int kb = kk * 8;
            uint32_t a[4];
            a[0] = sP[(r0 + g    ) * 68 + kb + t    ];
            a[1] = sP[(r0 + g + 8) * 68 + kb + t    ];
            a[2] = sP[(r0 + g    ) * 68 + kb + t + 4];
            a[3] = sP[(r0 + g + 8) * 68 + kb + t + 4];
            #pragma unroll
            for (int nt = 0; nt < 16; nt++) {
                uint2 bv = *reinterpret_cast<uint2*>(
                    &sVT[(nt * 8 + g) * 68 + kb + 2 * t]);
                mma_tf32(o[nt], a, reinterpret_cast<uint32_t*>(&bv));
            }
        }
    }

    // ---- store partials ----
    int qlo = q0 + r0 + g;
    float* pO = g_pO + (size_t)half * ((size_t)NM * NHS);
    size_t ro1 = (rowbase + qlo) * NHS;
    size_t ro2 = ro1 + (size_t)8 * NHS;
    #pragma unroll
    for (int nt = 0; nt < 16; nt++) {
        *reinterpret_cast<float2*>(&pO[ro1 + nt * 8 + 2 * t]) =
            make_float2(o[nt][0], o[nt][1]);
        *reinterpret_cast<float2*>(&pO[ro2 + nt * 8 + 2 * t]) =
            make_float2(o[nt][2], o[nt][3]);
    }
    if (t == 0) {
        size_t mi = (size_t)half * NM + rowbase + qlo;
        g_pm[mi] = m_lo;   g_pm[mi + 8] = m_hi;
        g_pl[mi] = l_lo;   g_pl[mi + 8] = l_hi;
    }
}

// ---------------------------------------------------------------------------
// attn_merge                                                    (launch #5)
// ---------------------------------------------------------------------------
__global__ __launch_bounds__(256) void attn_merge(float* __restrict__ out)
{
    int i4 = blockIdx.x * 256 + threadIdx.x;
    int row = i4 >> 5;
    float m0 = g_pm[row], m1 = g_pm[NM + row];
    float mM = fmaxf(m0, m1);
    float e0 = exp2f(m0 - mM), e1 = exp2f(m1 - mM);
    float inv = 1.f / (g_pl[row] * e0 + g_pl[NM + row] * e1);
    float4 a = *reinterpret_cast<float4*>(&g_pO[(size_t)i4 * 4]);
    float4 b = *reinterpret_cast<float4*>(&g_pO[(size_t)NM * NHS + (size_t)i4 * 4]);
    float4 r;
    r.x = (a.x * e0 + b.x * e1) * inv;
    r.y = (a.y * e0 + b.y * e1) * inv;
    r.z = (a.z * e0 + b.z * e1) * inv;
    r.w = (a.w * e0 + b.w * e1) * inv;
    *reinterpret_cast<float4*>(&out[(size_t)i4 * 4]) = r;
}

// ---------------------------------------------------------------------------
extern "C" void kernel_launch(void* const* d_in, const int* in_sizes, int n_in,
                              void* d_out, int out_size)
{
    const float* x  = (const float*)d_in[0];
    const float* Wk = (const float*)d_in[1];
    const float* Wq = (const float*)d_in[2];
    const float* Wv = (const float*)d_in[3];
    float* out = (float*)d_out;

    (void)in_sizes; (void)n_in; (void)out_size;

    cudaFuncSetAttribute(attn_mma,
                         cudaFuncAttributeMaxDynamicSharedMemorySize,
                         ATTN_SMEM_BYTES);
    cudaFuncSetAttribute(proj_cp,
                         cudaFuncAttributeMaxDynamicSharedMemorySize,
                         PROJ_SMEM);

    rope_table_kernel<<<(NT * 64 + 255) / 256, 256>>>();          // #1
    prep_w<<<dim3(NC / 32, 3), 256>>>(Wk, Wq, Wv);                // #2
    proj_cp<<<dim3(NM / 128, 3), 256, PROJ_SMEM>>>(x);            // #3
    attn_mma<<<256, 256, ATTN_SMEM_BYTES>>>();                    // #4 (profiled)
    attn_merge<<<2048, 256>>>(out);                               // #5
}

// round 17
// speedup vs baseline: 1.0764x; 1.0764x over previous
#include <cuda_runtime.h>
#include <math.h>
#include <stdint.h>

#define NB 8
#define NT 2048
#define NC 2048
#define NHS 128
#define NM (NB*NT)

// scratch
__device__ uint32_t g_qh[(size_t)NM*64];              // q bf16-hi, pair-permuted, pre-scaled
__device__ uint32_t g_ql[(size_t)NM*64];              // q bf16-lo
__device__ uint32_t g_kh[(size_t)NM*64];              // k bf16-hi
__device__ uint32_t g_kl[(size_t)NM*64];              // k bf16-lo
__device__ float g_vT[(size_t)NB*NHS*NT];             // v^T, tf32-rounded, vmap key order
__device__ float g_cos[NT*64];
__device__ float g_sin[NT*64];
__device__ float g_wp[(size_t)3*NC*NHS];              // W, fragment-permuted + tf32-rounded
__device__ float g_pO[(size_t)2*NM*NHS];              // split-KV partial O
__device__ float g_pm[2*NM];                          // partial row max
__device__ float g_pl[2*NM];                          // partial row sum

__device__ __forceinline__ uint32_t f2tf(float f) {
    uint32_t r;
    asm("cvt.rna.tf32.f32 %0, %1;" : "=r"(r) : "f"(f));
    return r;
}
__device__ __forceinline__ float tf32r(float f) {
    return __uint_as_float(f2tf(f));
}
__device__ __forceinline__ uint32_t bfpack(float lo, float hi) {
    uint32_t r;   // lo -> bits 0-15, hi -> bits 16-31
    asm("cvt.rn.bf16x2.f32 %0, %1, %2;" : "=r"(r) : "f"(hi), "f"(lo));
    return r;
}

__device__ __forceinline__ void mma_tf32(float c[4], const uint32_t a[4],
                                         const uint32_t b[2]) {
    asm volatile(
        "mma.sync.aligned.m16n8k8.row.col.f32.tf32.tf32.f32 "
        "{%0,%1,%2,%3}, {%4,%5,%6,%7}, {%8,%9}, {%0,%1,%2,%3};"
        : "+f"(c[0]), "+f"(c[1]), "+f"(c[2]), "+f"(c[3])
        : "r"(a[0]), "r"(a[1]), "r"(a[2]), "r"(a[3]),
          "r"(b[0]), "r"(b[1]));
}
__device__ __forceinline__ void mma_bf16(float c[4], const uint32_t a[4],
                                         const uint32_t b[2]) {
    asm volatile(
        "mma.sync.aligned.m16n8k16.row.col.f32.bf16.bf16.f32 "
        "{%0,%1,%2,%3}, {%4,%5,%6,%7}, {%8,%9}, {%0,%1,%2,%3};"
        : "+f"(c[0]), "+f"(c[1]), "+f"(c[2]), "+f"(c[3])
        : "r"(a[0]), "r"(a[1]), "r"(a[2]), "r"(a[3]),
          "r"(b[0]), "r"(b[1]));
}

__device__ __forceinline__ uint32_t smem_u32(const void* p) {
    uint32_t a;
    asm("{ .reg .u64 t; cvta.to.shared.u64 t, %1; cvt.u32.u64 %0, t; }"
        : "=r"(a) : "l"(p));
    return a;
}

__device__ __forceinline__ void cp16(uint32_t dst, const void* src) {
    asm volatile("cp.async.cg.shared.global [%0], [%1], 16;"
                 :: "r"(dst), "l"(src) : "memory");
}
#define CP_COMMIT() asm volatile("cp.async.commit_group;" ::: "memory")
#define CP_WAIT(n)  asm volatile("cp.async.wait_group %0;" :: "n"(n) : "memory")

// pair layout: word(row, fp) holds bf16x2 of features {2fp, 2fp+1};
// q = 8*(fp>>3) + 2*(fp&3) + ((fp>>2)&1)  (bijective onto [0,64)).
__device__ __forceinline__ int qmap(int fp) {
    return 8 * (fp >> 3) + 2 * (fp & 3) + ((fp >> 2) & 1);
}
__device__ __forceinline__ int swz(int q, int row) {
    return q ^ ((q >> 2) & 0x18) ^ ((row & 3) << 3);
}
// V key permute within 64-chunk: keys (8k+t, 8k+t+4) become adjacent words.
__device__ __forceinline__ int vmap(int kl) {
    return (kl & ~7) + ((kl & 3) << 1) + ((kl >> 2) & 1);
}

// ---------------------------------------------------------------------------
// RoPE tables                                                   (launch #1)
// ---------------------------------------------------------------------------
__global__ void rope_table_kernel()
{
    int idx = blockIdx.x * 256 + threadIdx.x;
    if (idx >= NT * 64) return;
    int tt = idx >> 6, p = idx & 63;
    const float L2T = 13.287712379549449f / 64.f;   // log2(10000)/64
    float freq = exp2f(-(float)p * L2T);
    float sn, cs;
    sincosf((float)tt * freq, &sn, &cs);
    g_cos[idx] = cs;
    g_sin[idx] = sn;
}

// ---------------------------------------------------------------------------
// prep_w                                                        (launch #2)
// ---------------------------------------------------------------------------
#define PWSTR 136
__global__ __launch_bounds__(256) void prep_w(
    const float* __restrict__ Wk, const float* __restrict__ Wq,
    const float* __restrict__ Wv)
{
    __shared__ float s[32 * PWSTR];
    const int tid = threadIdx.x;
    const int kit = blockIdx.x, which = blockIdx.y;
    const float* W = (which == 0) ? Wk : (which == 1) ? Wq : Wv;

    #pragma unroll
    for (int u = 0; u < 4; u++) {
        int flat = u * 256 + tid;
        int row = flat >> 5, cf = flat & 31;
        float4 v = *reinterpret_cast<const float4*>(
            &W[(size_t)(kit * 32 + row) * NHS + cf * 4]);
        *reinterpret_cast<float4*>(&s[row * PWSTR + cf * 4]) = v;
    }
    __syncthreads();

    const size_t base = ((size_t)(which * 64 + kit)) * 4096;
    #pragma unroll
    for (int u = 0; u < 8; u++) {
        int pid = u * 256 + tid;
        int lane = pid & 31, ks = (pid >> 5) & 3, in = (pid >> 7) & 3, wn = pid >> 9;
        int g = lane >> 2, t = lane & 3;
        int n0 = wn * 32 + in * 8 + g, c = ks * 8 + t;
        float2 o;
        o.x = tf32r(s[(c    ) * PWSTR + n0]);
        o.y = tf32r(s[(c + 4) * PWSTR + n0]);
        *reinterpret_cast<float2*>(&g_wp[base + (size_t)pid * 2]) = o;
    }
}

// ---------------------------------------------------------------------------
// Kernel A: fused projection + RoPE; epilogue emits attn-ready  (launch #3)
// formats: q/k as bf16 hi/lo pair-permuted, v^T tf32 + vmap.
// ---------------------------------------------------------------------------
#define AQW 4096
#define BQW 4096
#define PROJ_SMEM ((2*AQW + 3*BQW)*4)
#define NITER (NC/32)

__global__ __launch_bounds__(256, 2) void proj_cp(const float* __restrict__ x)
{
    extern __shared__ float sm[];
    const uint32_t sbase = smem_u32(sm);
    const uint32_t sA0 = sbase;
    const uint32_t sB0 = sbase + 2 * AQW * 4;

    const int tid  = threadIdx.x;
    const int warp = tid >> 5, lane = tid & 31;
    const int wm = warp >> 2, wn = warp & 3;
    const int g = lane >> 2, t = lane & 3;
    const int mtile = blockIdx.x, which = blockIdx.y;
    const int mbase = mtile * 128;

    const int im_s = warp & 3;
    const size_t arow0 = (size_t)(mbase + wm * 64 + im_s * 16 + g) * NC;
    const size_t arow8 = arow0 + (size_t)8 * NC;
    const int akc = t * 8;
    uint32_t asts[4];
    #pragma unroll
    for (int tt = 0; tt < 4; tt++)
        asts[tt] = (uint32_t)((((wm * 4 + im_s) * 4 + t) * 32 +
                               ((g * 4 + tt) ^ t)) * 16);

    const float* wp = &g_wp[((size_t)which * 64) * 4096];

    float c[4][4][4];
    #pragma unroll
    for (int im = 0; im < 4; im++)
        #pragma unroll
        for (int in = 0; in < 4; in++)
            #pragma unroll
            for (int f = 0; f < 4; f++) c[im][in][f] = 0.f;

    float4 f0, f1, f2, f3;
    auto ldgA = [&](int it) {
        const int kc = it * 32 + akc;
        f0 = *reinterpret_cast<const float4*>(&x[arow0 + kc]);
        f1 = *reinterpret_cast<const float4*>(&x[arow0 + kc + 4]);
        f2 = *reinterpret_cast<const float4*>(&x[arow8 + kc]);
        f3 = *reinterpret_cast<const float4*>(&x[arow8 + kc + 4]);
    };
    auto stsA = [&](int buf) {
        const uint32_t base = sA0 + (uint32_t)buf * (AQW * 4);
        const float a0[4] = {f0.x, f0.y, f0.z, f0.w};
        const float a1[4] = {f1.x, f1.y, f1.z, f1.w};
        const float a2[4] = {f2.x, f2.y, f2.z, f2.w};
        const float a3[4] = {f3.x, f3.y, f3.z, f3.w};
        #pragma unroll
        for (int tt = 0; tt < 4; tt++) {
            uint32_t qx = f2tf(a0[tt]), qy = f2tf(a2[tt]);
            uint32_t qz = f2tf(a1[tt]), qw = f2tf(a3[tt]);
            asm volatile("st.shared.v4.b32 [%0], {%1,%2,%3,%4};"
                         :: "r"(base + asts[tt]),
                            "r"(qx), "r"(qy), "r"(qz), "r"(qw) : "memory");
        }
    };
    auto stageB = [&](int it, int s) {
        const uint32_t bb = sB0 + (uint32_t)s * (BQW * 4);
        const float* wt = wp + (size_t)it * 4096;
        #pragma unroll
        for (int u = 0; u < 4; u++) {
            int idx = u * 256 + tid;
            cp16(bb + (uint32_t)idx * 16, wt + idx * 4);
        }
        CP_COMMIT();
    };

    stageB(0, 0);
    stageB(1, 1);
    ldgA(0);

    for (int it = 0; it < NITER; it++) {
        stsA(it & 1);
        if (it == NITER - 1) { CP_WAIT(0); } else { CP_WAIT(1); }
        __syncthreads();
        if (it + 1 < NITER) ldgA(it + 1);
        if (it + 2 < NITER) stageB(it + 2, (it + 2) % 3);

        const uint32_t aB = sA0 + (uint32_t)(it & 1) * (AQW * 4);
        const uint32_t bB = sB0 + (uint32_t)(it % 3) * (BQW * 4);

        #pragma unroll
        for (int ks = 0; ks < 4; ks++) {
            uint32_t afr[4][4];
            #pragma unroll
            for (int im = 0; im < 4; im++) {
                uint32_t ad = aB + (uint32_t)((((wm * 4 + im) * 4 + ks) * 32 +
                                               (lane ^ ks)) * 16);
                asm volatile("ld.shared.v4.b32 {%0,%1,%2,%3}, [%4];"
                             : "=r"(afr[im][0]), "=r"(afr[im][1]),
                               "=r"(afr[im][2]), "=r"(afr[im][3])
                             : "r"(ad));
            }
            uint32_t bfr[4][2];
            #pragma unroll
            for (int in = 0; in < 4; in++) {
                uint32_t bd = bB + (uint32_t)((((wn * 4 + in) * 4 + ks) * 32 +
                                               lane) * 8);
                asm volatile("ld.shared.v2.b32 {%0,%1}, [%2];"
                             : "=r"(bfr[in][0]), "=r"(bfr[in][1])
                             : "r"(bd));
            }
            #pragma unroll
            for (int im = 0; im < 4; im++)
                #pragma unroll
                for (int in = 0; in < 4; in++)
                    mma_tf32(c[im][in], afr[im], bfr[in]);
        }
    }

    // epilogue -> attn-ready formats
    const float qs = 0.08838834764831845f * 1.4426950408889634f;
    #pragma unroll
    for (int im = 0; im < 4; im++) {
        int r1 = mbase + wm * 64 + im * 16 + g;
        int r2 = r1 + 8;
        int bb = r1 >> 11;
        int t1 = r1 & (NT - 1), t2 = r2 & (NT - 1);
        if (which == 2) {
            int p1 = (t1 & ~63) + vmap(t1 & 63);
            int p2 = (t2 & ~63) + vmap(t2 & 63);
            #pragma unroll
            for (int in = 0; in < 4; in++) {
                int n = wn * 32 + in * 8 + 2 * t;
                size_t b0 = ((size_t)bb * NHS + n) * NT;
                size_t b1 = ((size_t)bb * NHS + n + 1) * NT;
                g_vT[b0 + p1] = tf32r(c[im][in][0]);
                g_vT[b1 + p1] = tf32r(c[im][in][1]);
                g_vT[b0 + p2] = tf32r(c[im][in][2]);
                g_vT[b1 + p2] = tf32r(c[im][in][3]);
            }
        } else {
            uint32_t* oh = (which == 1) ? g_qh : g_kh;
            uint32_t* ol = (which == 1) ? g_ql : g_kl;
            #pragma unroll
            for (int in2 = 0; in2 < 4; in2 += 2) {
                uint32_t h1[2], l1[2], h2[2], l2[2];
                #pragma unroll
                for (int j = 0; j < 2; j++) {
                    int in = in2 + j;
                    int n = wn * 32 + in * 8 + 2 * t;
                    int p = n >> 1;
                    float cs1 = g_cos[t1 * 64 + p], sn1 = g_sin[t1 * 64 + p];
                    float cs2 = g_cos[t2 * 64 + p], sn2 = g_sin[t2 * 64 + p];
                    float e0 = c[im][in][0] * cs1 - c[im][in][1] * sn1;
                    float e1 = c[im][in][0] * sn1 + c[im][in][1] * cs1;
                    float d0 = c[im][in][2] * cs2 - c[im][in][3] * sn2;
                    float d1 = c[im][in][2] * sn2 + c[im][in][3] * cs2;
                    if (which == 1) { e0 *= qs; e1 *= qs; d0 *= qs; d1 *= qs; }
                    uint32_t hh = bfpack(e0, e1);
                    h1[j] = hh;
                    l1[j] = bfpack(e0 - __uint_as_float(hh << 16),
                                   e1 - __uint_as_float(hh & 0xffff0000u));
                    hh = bfpack(d0, d1);
                    h2[j] = hh;
                    l2[j] = bfpack(d0 - __uint_as_float(hh << 16),
                                   d1 - __uint_as_float(hh & 0xffff0000u));
                }
                int w = qmap((wn * 32 + in2 * 8 + 2 * t) >> 1);
                *reinterpret_cast<uint2*>(&oh[(size_t)r1 * 64 + w]) = make_uint2(h1[0], h1[1]);
                *reinterpret_cast<uint2*>(&ol[(size_t)r1 * 64 + w]) = make_uint2(l1[0], l1[1]);
                *reinterpret_cast<uint2*>(&oh[(size_t)r2 * 64 + w]) = make_uint2(h2[0], h2[1]);
                *reinterpret_cast<uint2*>(&ol[(size_t)r2 * 64 + w]) = make_uint2(l2[0], l2[1]);
            }
        }
    }
}

// ---------------------------------------------------------------------------
// Kernel B: causal flash attention, split-KV 2-way.             (launch #4)
// Q fragments live in registers; K/V double-buffered cp.async with
// one-chunk prefetch. P round-trips smem (warp-local).
// ---------------------------------------------------------------------------
#define SKH 0
#define SKL 4096
#define SVT 8192
#define STG 16896                      // words per K+V stage
#define PP0 (2*STG)                    // 33792
#define ATTN_SMEM_BYTES ((PP0 + 8704) * 4)

__global__ __launch_bounds__(256) void attn_mma()
{
    extern __shared__ char smem_raw[];
    const uint32_t sb = smem_u32(smem_raw);
    uint32_t* sAll = (uint32_t*)smem_raw;
    uint32_t* sP   = sAll + PP0;

    const int tid  = threadIdx.x;
    const int warp = tid >> 5, lane = tid & 31;
    const int g = lane >> 2, t = lane & 3;
    const int r0 = warp * 16;

    const int bx = blockIdx.x;
    const int qi   = 15 - (bx >> 4);          // largest tiles first (LPT)
    const int yb   = (bx >> 1) & 7;
    const int half = bx & 1;
    const int q0 = qi * 128;
    const int c0 = half * (qi + 1);
    const size_t rowbase = (size_t)yb * NT;

    // ---- K/V staging (cp.async into stage buffer s) ----
    auto stageKV = [&](int c, int s) {
        const uint32_t base = sb + (uint32_t)(s * STG) * 4;
        const size_t ksrc = (size_t)(rowbase + c * 64) * 64;
        #pragma unroll
        for (int u = 0; u < 4; u++) {
            int id = u * 256 + tid;
            int row = id >> 4, grp = (id & 15) * 4;
            uint32_t woff = (uint32_t)(row * 64 + swz(grp, row));
            cp16(base + (SKH + woff) * 4, &g_kh[ksrc + (size_t)row * 64 + grp]);
            cp16(base + (SKL + woff) * 4, &g_kl[ksrc + (size_t)row * 64 + grp]);
        }
        const float* vsrc = &g_vT[(size_t)yb * NHS * NT + (size_t)c * 64];
        #pragma unroll
        for (int u = 0; u < 8; u++) {
            int id = u * 256 + tid;
            int hr = id >> 4, kf = (id & 15) * 4;
            cp16(base + (uint32_t)(SVT + hr * 68 + kf) * 4,
                 vsrc + (size_t)hr * NT + kf);
        }
        CP_COMMIT();
    };

    stageKV(c0, 0);

    // ---- load Q fragments into registers (one-time LDG) ----
    uint32_t qh_[8][4], ql_[8][4];
    {
        const size_t rq1 = (rowbase + q0 + r0 + g) * 64;
        const size_t rq2 = rq1 + 8 * 64;
        #pragma unroll
        for (int kst = 0; kst < 8; kst++) {
            int qa = 8 * kst + 2 * t;
            uint2 v;
            v = *reinterpret_cast<const uint2*>(&g_qh[rq1 + qa]);
            qh_[kst][0] = v.x; qh_[kst][2] = v.y;
            v = *reinterpret_cast<const uint2*>(&g_qh[rq2 + qa]);
            qh_[kst][1] = v.x; qh_[kst][3] = v.y;
            v = *reinterpret_cast<const uint2*>(&g_ql[rq1 + qa]);
            ql_[kst][0] = v.x; ql_[kst][2] = v.y;
            v = *reinterpret_cast<const uint2*>(&g_ql[rq2 + qa]);
            ql_[kst][1] = v.x; ql_[kst][3] = v.y;
        }
    }

    float m_lo = -1e30f, m_hi = -1e30f, l_lo = 0.f, l_hi = 0.f;
    float o[16][4];
    #pragma unroll
    for (int nt = 0; nt < 16; nt++)
        #pragma unroll
        for (int f = 0; f < 4; f++) o[nt][f] = 0.f;

    for (int ci = 0; ci <= qi; ci++) {
        const int c = c0 + ci;
        const int buf = ci & 1;
        // prefetch next chunk into the other buffer, then wait for this one
        if (ci < qi) { stageKV(c + 1, buf ^ 1); CP_WAIT(1); }
        else         { CP_WAIT(0); }
        __syncthreads();                        // (a) staged data visible

        uint32_t* sKh = sAll + buf * STG + SKH;
        uint32_t* sKl = sAll + buf * STG + SKL;
        uint32_t* sVT = sAll + buf * STG + SVT;

        // ---- S = QK^T (bf16 split, m16n8k16; Q from regs) ----
        float s[8][4];
        #pragma unroll
        for (int in = 0; in < 8; in++)
            #pragma unroll
            for (int f = 0; f < 4; f++) s[in][f] = 0.f;

        #pragma unroll
        for (int kst = 0; kst < 8; kst++) {
            const int qa = 8 * kst + 2 * t;
            #pragma unroll
            for (int in = 0; in < 8; in++) {
                int key = in * 8 + g;
                int w = key * 64 + swz(qa, key);
                uint2 bh = *reinterpret_cast<uint2*>(sKh + w);
                uint2 bl = *reinterpret_cast<uint2*>(sKl + w);
                mma_bf16(s[in], qh_[kst], reinterpret_cast<uint32_t*>(&bh));
                mma_bf16(s[in], qh_[kst], reinterpret_cast<uint32_t*>(&bl));
                mma_bf16(s[in], ql_[kst], reinterpret_cast<uint32_t*>(&bh));
            }
        }

        // causal mask
        if (c >= 2 * qi) {
            int qlo = q0 + r0 + g, qhi = qlo + 8;
            int k0c = c * 64;
            #pragma unroll
            for (int in = 0; in < 8; in++) {
                int key0 = k0c + in * 8 + 2 * t;
                if (key0     > qlo) s[in][0] = -1e30f;
                if (key0 + 1 > qlo) s[in][1] = -1e30f;
                if (key0     > qhi) s[in][2] = -1e30f;
                if (key0 + 1 > qhi) s[in][3] = -1e30f;
            }
        }

        // ---- online softmax ----
        float mxl = -1e30f, mxh = -1e30f;
        #pragma unroll
        for (int in = 0; in < 8; in++) {
            mxl = fmaxf(mxl, fmaxf(s[in][0], s[in][1]));
            mxh = fmaxf(mxh, fmaxf(s[in][2], s[in][3]));
        }
        mxl = fmaxf(mxl, __shfl_xor_sync(0xffffffffu, mxl, 1));
        mxl = fmaxf(mxl, __shfl_xor_sync(0xffffffffu, mxl, 2));
        mxh = fmaxf(mxh, __shfl_xor_sync(0xffffffffu, mxh, 1));
        mxh = fmaxf(mxh, __shfl_xor_sync(0xffffffffu, mxh, 2));

        float mnl = fmaxf(fmaxf(m_lo, mxl), -1e20f);
        float mnh = fmaxf(fmaxf(m_hi, mxh), -1e20f);
        float facl = exp2f(m_lo - mnl), fach = exp2f(m_hi - mnh);
        m_lo = mnl; m_hi = mnh;

        float suml = 0.f, sumh = 0.f;
        #pragma unroll
        for (int in = 0; in < 8; in++) {
            float p0 = exp2f(s[in][0] - mnl);
            float p1 = exp2f(s[in][1] - mnl);
            float p2 = exp2f(s[in][2] - mnh);
            float p3 = exp2f(s[in][3] - mnh);
            suml += p0 + p1; sumh += p2 + p3;
            uint2 w0; w0.x = f2tf(p0); w0.y = f2tf(p1);
            uint2 w1; w1.x = f2tf(p2); w1.y = f2tf(p3);
            *reinterpret_cast<uint2*>(&sP[(r0 + g    ) * 68 + in * 8 + 2 * t]) = w0;
            *reinterpret_cast<uint2*>(&sP[(r0 + g + 8) * 68 + in * 8 + 2 * t]) = w1;
        }
        suml += __shfl_xor_sync(0xffffffffu, suml, 1);
        suml += __shfl_xor_sync(0xffffffffu, suml, 2);
        sumh += __shfl_xor_sync(0xffffffffu, sumh, 1);
        sumh += __shfl_xor_sync(0xffffffffu, sumh, 2);
        l_lo = l_lo * facl + suml;
        l_hi = l_hi * fach + sumh;

        // rescale O only if some row max moved (exp2f(0)==1 exact)
        bool nochg = (facl == 1.f) && (fach == 1.f);
        if (__ballot_sync(0xffffffffu, nochg) != 0xffffffffu) {
            #pragma unroll
            for (int nt = 0; nt < 16; nt++) {
                o[nt][0] *= facl; o[nt][1] *= facl;
                o[nt][2] *= fach; o[nt][3] *= fach;
            }
        }
        __syncwarp();

        // ---- O += P V (tf32 k8, vmap-paired b loads) ----
        #pragma unroll
        for (int kk = 0; kk < 8; kk++) {
            int kb = kk * 8;
            uint32_t a[4];
            a[0] = sP[(r0 + g    ) * 68 + kb + t    ];
            a[1] = sP[(r0 + g + 8) * 68 + kb + t    ];
            a[2] = sP[(r0 + g    ) * 68 + kb + t + 4];
            a[3] = sP[(r0 + g + 8) * 68 + kb + t + 4];
            #pragma unroll
            for (int nt = 0; nt < 16; nt++) {
                uint2 bv = *reinterpret_cast<uint2*>(
                    &sVT[(nt * 8 + g) * 68 + kb + 2 * t]);
                mma_tf32(o[nt], a, reinterpret_cast<uint32_t*>(&bv));
            }
        }
        __syncthreads();                        // (b) buffer drained before reuse
    }

    // ---- store partials ----
    int qlo = q0 + r0 + g;
    float* pO = g_pO + (size_t)half * ((size_t)NM * NHS);
    size_t ro1 = (rowbase + qlo) * NHS;
    size_t ro2 = ro1 + (size_t)8 * NHS;
    #pragma unroll
    for (int nt = 0; nt < 16; nt++) {
        *reinterpret_cast<float2*>(&pO[ro1 + nt * 8 + 2 * t]) =
            make_float2(o[nt][0], o[nt][1]);
        *reinterpret_cast<float2*>(&pO[ro2 + nt * 8 + 2 * t]) =
            make_float2(o[nt][2], o[nt][3]);
    }
    if (t == 0) {
        size_t mi = (size_t)half * NM + rowbase + qlo;
        g_pm[mi] = m_lo;   g_pm[mi + 8] = m_hi;
        g_pl[mi] = l_lo;   g_pl[mi + 8] = l_hi;
    }
}

// ---------------------------------------------------------------------------
// attn_merge                                                    (launch #5)
// ---------------------------------------------------------------------------
__global__ __launch_bounds__(256) void attn_merge(float* __restrict__ out)
{
    int i4 = blockIdx.x * 256 + threadIdx.x;
    int row = i4 >> 5;
    float m0 = g_pm[row], m1 = g_pm[NM + row];
    float mM = fmaxf(m0, m1);
    float e0 = exp2f(m0 - mM), e1 = exp2f(m1 - mM);
    float inv = 1.f / (g_pl[row] * e0 + g_pl[NM + row] * e1);
    float4 a = *reinterpret_cast<float4*>(&g_pO[(size_t)i4 * 4]);
    float4 b = *reinterpret_cast<float4*>(&g_pO[(size_t)NM * NHS + (size_t)i4 * 4]);
    float4 r;
    r.x = (a.x * e0 + b.x * e1) * inv;
    r.y = (a.y * e0 + b.y * e1) * inv;
    r.z = (a.z * e0 + b.z * e1) * inv;
    r.w = (a.w * e0 + b.w * e1) * inv;
    *reinterpret_cast<float4*>(&out[(size_t)i4 * 4]) = r;
}

// ---------------------------------------------------------------------------
extern "C" void kernel_launch(void* const* d_in, const int* in_sizes, int n_in,
                              void* d_out, int out_size)
{
    const float* x  = (const float*)d_in[0];
    const float* Wk = (const float*)d_in[1];
    const float* Wq = (const float*)d_in[2];
    const float* Wv = (const float*)d_in[3];
    float* out = (float*)d_out;

    (void)in_sizes; (void)n_in; (void)out_size;

    cudaFuncSetAttribute(attn_mma,
                         cudaFuncAttributeMaxDynamicSharedMemorySize,
                         ATTN_SMEM_BYTES);
    cudaFuncSetAttribute(proj_cp,
                         cudaFuncAttributeMaxDynamicSharedMemorySize,
                         PROJ_SMEM);

    rope_table_kernel<<<(NT * 64 + 255) / 256, 256>>>();          // #1
    prep_w<<<dim3(NC / 32, 3), 256>>>(Wk, Wq, Wv);                // #2
    proj_cp<<<dim3(NM / 128, 3), 256, PROJ_SMEM>>>(x);            // #3
    attn_mma<<<256, 256, ATTN_SMEM_BYTES>>>();                    // #4 (profiled)
    attn_merge<<<2048, 256>>>(out);                               // #5
}